// round 3
// baseline (speedup 1.0000x reference)
#include <cuda_runtime.h>
#include <math.h>

// Problem shape (fixed): B=8, C=64, T=16, H=64, W=64, text_dim=768
#define NB 8
#define NC 64
#define NT 16
#define HW2 2048         // H*W/2 (float2 units per T-plane)
#define TD 768
#define NBC (NB*NC)      // 512

// Per-(b,c,t) sigmoid gates
__device__ float g_w[NBC * NT];   // 32 KB

// ---------------------------------------------------------------------------
// Kernel 1: gates only.  One block per (b,c); 16 groups of 16 threads, one
// 768-length dot each.
// ---------------------------------------------------------------------------
__global__ __launch_bounds__(256) void gate_kernel(
    const float* __restrict__ E,    // (B, 768)
    const float* __restrict__ Wf,   // (C*T, 768)
    const float* __restrict__ bf)   // (C*T,)
{
    const int bc = blockIdx.x;
    const int b = bc >> 6;
    const int c = bc & 63;
    const int g = threadIdx.x >> 4;      // dot index 0..15
    const int l = threadIdx.x & 15;      // lane within group

    const int j = c * NT + g;
    const float4* e4 = (const float4*)(E  + (size_t)b * TD);
    const float4* w4 = (const float4*)(Wf + (size_t)j * TD);

    float s = 0.0f;
    #pragma unroll
    for (int d = l; d < TD / 4; d += 16) {       // 12 float4 per thread
        const float4 ev = e4[d];
        const float4 wv = w4[d];
        s = fmaf(ev.x, wv.x, s);
        s = fmaf(ev.y, wv.y, s);
        s = fmaf(ev.z, wv.z, s);
        s = fmaf(ev.w, wv.w, s);
    }
    #pragma unroll
    for (int o = 8; o; o >>= 1) s += __shfl_xor_sync(0xffffffffu, s, o);
    if (l == 0) {
        const float z = s + bf[j];
        g_w[bc * NT + g] = 1.0f / (1.0f + expf(-z));
    }
}

// ---------------------------------------------------------------------------
// Kernel 2: streaming modulation, float2 per thread, M built in the prologue
// (hidden under the 16 in-flight DRAM loads).  Grid (512, 8); 256 threads.
// ---------------------------------------------------------------------------
__global__ __launch_bounds__(256, 3) void mod_kernel(
    const unsigned long long* __restrict__ r,   // f32x2 view of r
    unsigned long long* __restrict__ out)
{
    __shared__ float sw[NT];
    __shared__ float sD[NT][NT];
    __shared__ unsigned long long sM[NT][NT];   // duplicated (m,m) pairs, 2 KB

    const int bc = blockIdx.x;
    const int u = blockIdx.y * 256 + threadIdx.x;        // [0, 2048)
    const size_t base = (size_t)bc * (NT * HW2) + u;

    // Front-batched streaming loads: 16 independent LDG.64 (MLP=16)
    unsigned long long x[NT];
    #pragma unroll
    for (int k = 0; k < NT; k++)
        x[k] = __ldcs(r + base + (size_t)k * HW2);

    // ---- prologue: build M = D^T diag(w) D while loads are in flight ----
    if (threadIdx.x < NT) sw[threadIdx.x] = g_w[bc * NT + threadIdx.x];
    {
        const int k = threadIdx.x >> 4;
        const int t = threadIdx.x & 15;
        const float sc = (k == 0) ? 0.25f : 0.35355339059327373f; // sqrt(1/16), sqrt(2/16)
        sD[k][t] = cosf(3.14159265358979323846f * ((float)t + 0.5f) * (float)k / 16.0f) * sc;
    }
    __syncthreads();
    {
        const int to = threadIdx.x >> 4;
        const int ti = threadIdx.x & 15;
        float acc = 0.0f;
        #pragma unroll
        for (int k = 0; k < NT; k++)
            acc = fmaf(sD[k][to] * sw[k], sD[k][ti], acc);
        *(float2*)&sM[to][ti] = make_float2(acc, acc);
    }
    __syncthreads();

    // ---- matvec: y[t] = sum_k M[t][k] * x[k], packed f32x2 ----
    #pragma unroll
    for (int t = 0; t < NT; t++) {
        unsigned long long a0 = 0ull, a1 = 0ull;
        #pragma unroll
        for (int k2 = 0; k2 < NT / 2; k2++) {
            const ulonglong2 m = *(const ulonglong2*)&sM[t][2 * k2];  // LDS.128
            asm("fma.rn.f32x2 %0, %1, %2, %0;" : "+l"(a0) : "l"(m.x), "l"(x[2 * k2]));
            asm("fma.rn.f32x2 %0, %1, %2, %0;" : "+l"(a1) : "l"(m.y), "l"(x[2 * k2 + 1]));
        }
        unsigned long long a;
        asm("add.rn.f32x2 %0, %1, %2;" : "=l"(a) : "l"(a0), "l"(a1));
        __stcs(out + base + (size_t)t * HW2, a);
    }
}

// ---------------------------------------------------------------------------
extern "C" void kernel_launch(void* const* d_in, const int* in_sizes, int n_in,
                              void* d_out, int out_size)
{
    const float* r  = (const float*)d_in[0];   // (8,64,16,64,64)
    const float* E  = (const float*)d_in[1];   // (8,768)
    const float* Wf = (const float*)d_in[2];   // (1024,768)
    const float* bf = (const float*)d_in[3];   // (1024,)
    float* out = (float*)d_out;

    gate_kernel<<<NBC, 256>>>(E, Wf, bf);

    dim3 grid(NBC, 8);
    mod_kernel<<<grid, 256>>>((const unsigned long long*)r,
                              (unsigned long long*)out);
}

// round 4
// speedup vs baseline: 1.0231x; 1.0231x over previous
#include <cuda_runtime.h>
#include <math.h>

// Problem shape (fixed): B=8, C=64, T=16, H=64, W=64, text_dim=768
#define NB 8
#define NC 64
#define NT 16
#define HW4 1024         // H*W/4 (float4 / longlong2 units per T-plane)
#define TD 768
#define NBC (NB*NC)      // 512
#define PF 6             // load prefetch distance (planes)

// Per-(b,c,t) sigmoid gates
__device__ float g_w[NBC * NT];   // 32 KB

// ---------------------------------------------------------------------------
// Kernel 1: gates only.  One block per (b,c); 16 groups of 16 threads.
// ---------------------------------------------------------------------------
__global__ __launch_bounds__(256) void gate_kernel(
    const float* __restrict__ E,    // (B, 768)
    const float* __restrict__ Wf,   // (C*T, 768)
    const float* __restrict__ bf)   // (C*T,)
{
    const int bc = blockIdx.x;
    const int b = bc >> 6;
    const int c = bc & 63;
    const int g = threadIdx.x >> 4;      // dot index 0..15
    const int l = threadIdx.x & 15;      // lane within group

    const int j = c * NT + g;
    const float4* e4 = (const float4*)(E  + (size_t)b * TD);
    const float4* w4 = (const float4*)(Wf + (size_t)j * TD);

    float s = 0.0f;
    #pragma unroll
    for (int d = l; d < TD / 4; d += 16) {       // 12 float4 per thread
        const float4 ev = e4[d];
        const float4 wv = w4[d];
        s = fmaf(ev.x, wv.x, s);
        s = fmaf(ev.y, wv.y, s);
        s = fmaf(ev.z, wv.z, s);
        s = fmaf(ev.w, wv.w, s);
    }
    #pragma unroll
    for (int o = 8; o; o >>= 1) s += __shfl_xor_sync(0xffffffffu, s, o);
    if (l == 0) {
        const float z = s + bf[j];
        g_w[bc * NT + g] = 1.0f / (1.0f + expf(-z));
    }
}

// ---------------------------------------------------------------------------
// Kernel 2: streaming modulation.  Grid (512, 4); 256 threads; float4 columns.
// Accumulate-on-y ordering: x[k] consumed as it arrives (pipelined loads),
// 16 independent f32x2 accumulator pairs (no serial FMA chains).
// M = D^T diag(w) D built in the prologue, hidden under the first PF loads.
// ---------------------------------------------------------------------------
__global__ __launch_bounds__(256, 2) void mod_kernel(
    const longlong2* __restrict__ r,    // float4 planes as 2x f32x2
    longlong2* __restrict__ out)
{
    __shared__ float sw[NT];
    __shared__ float sD[NT][NT];
    __shared__ unsigned long long sM[NT][NT];   // duplicated (m,m) pairs, 2 KB

    const int bc = blockIdx.x;
    const int u = blockIdx.y * 256 + threadIdx.x;        // [0, 1024)
    const size_t base = (size_t)bc * (NT * HW4) + u;

    // Kick off the first PF plane loads (streaming, no L2 persistence needed)
    longlong2 x[NT];
    #pragma unroll
    for (int k = 0; k < PF; k++)
        x[k] = __ldcs(r + base + (size_t)k * HW4);

    // ---- prologue: build M while the first loads are in flight ----
    if (threadIdx.x < NT) sw[threadIdx.x] = g_w[bc * NT + threadIdx.x];
    {
        const int k = threadIdx.x >> 4;
        const int t = threadIdx.x & 15;
        const float sc = (k == 0) ? 0.25f : 0.35355339059327373f; // sqrt(1/16), sqrt(2/16)
        sD[k][t] = cosf(3.14159265358979323846f * ((float)t + 0.5f) * (float)k / 16.0f) * sc;
    }
    __syncthreads();
    {
        const int to = threadIdx.x >> 4;
        const int ti = threadIdx.x & 15;
        float acc = 0.0f;
        #pragma unroll
        for (int kk = 0; kk < NT; kk++)
            acc = fmaf(sD[kk][to] * sw[kk], sD[kk][ti], acc);
        *(float2*)&sM[to][ti] = make_float2(acc, acc);   // duplicated pair
    }
    __syncthreads();

    // ---- mainloop: y[t] += M[t][k] * x[k], k-streamed ----
    unsigned long long ylo[NT], yhi[NT];
    #pragma unroll
    for (int t = 0; t < NT; t++) { ylo[t] = 0ull; yhi[t] = 0ull; }

    #pragma unroll
    for (int k = 0; k < NT; k++) {
        if (k + PF < NT)
            x[k + PF] = __ldcs(r + base + (size_t)(k + PF) * HW4);

        const unsigned long long xl = (unsigned long long)x[k].x;
        const unsigned long long xh = (unsigned long long)x[k].y;

        // M column k == M row k (symmetric): 8 broadcast LDS.128
        #pragma unroll
        for (int t2 = 0; t2 < NT / 2; t2++) {
            const ulonglong2 m = *(const ulonglong2*)&sM[k][2 * t2];
            asm("fma.rn.f32x2 %0, %1, %2, %0;" : "+l"(ylo[2*t2  ]) : "l"(m.x), "l"(xl));
            asm("fma.rn.f32x2 %0, %1, %2, %0;" : "+l"(yhi[2*t2  ]) : "l"(m.x), "l"(xh));
            asm("fma.rn.f32x2 %0, %1, %2, %0;" : "+l"(ylo[2*t2+1]) : "l"(m.y), "l"(xl));
            asm("fma.rn.f32x2 %0, %1, %2, %0;" : "+l"(yhi[2*t2+1]) : "l"(m.y), "l"(xh));
        }
    }

    // ---- epilogue: 16 streaming STG.128 ----
    #pragma unroll
    for (int t = 0; t < NT; t++) {
        longlong2 y;
        y.x = (long long)ylo[t];
        y.y = (long long)yhi[t];
        __stcs(out + base + (size_t)t * HW4, y);
    }
}

// ---------------------------------------------------------------------------
extern "C" void kernel_launch(void* const* d_in, const int* in_sizes, int n_in,
                              void* d_out, int out_size)
{
    const float* r  = (const float*)d_in[0];   // (8,64,16,64,64)
    const float* E  = (const float*)d_in[1];   // (8,768)
    const float* Wf = (const float*)d_in[2];   // (1024,768)
    const float* bf = (const float*)d_in[3];   // (1024,)
    float* out = (float*)d_out;

    gate_kernel<<<NBC, 256>>>(E, Wf, bf);

    dim3 grid(NBC, 4);
    mod_kernel<<<grid, 256>>>((const longlong2*)r, (longlong2*)out);
}